// round 15
// baseline (speedup 1.0000x reference)
#include <cuda_runtime.h>
#include <math.h>

#define NBATCH 64
#define NANC   3
#define NCLS   13
#define NHH    76
#define NWW    76
#define NPIX   (NHH*NWW)          // 5776
#define NANCH  (NANC*NPIX)        // 17328
#define MAXT   50
#define NLV    12
#define NCH    (NLV+NCLS)         // 25
#define BETA_C 0.028f
#define NETWH  608.0f

#define G4PB    (NANCH/4)         // 4332 float4-groups per batch
#define G4TOT   (NBATCH*G4PB)     // 277248
#define SBLKS   361               // 361*256*3 == 277248 EXACT cover
#define NBLKS   (SBLKS+NBATCH)    // 425 blocks; <=3/SM -> single wave (<=444)
#define LISTCAP 32768

// anchors fixed: [[0.7,1.18],[1.26,2.1],[2.64,4.2]]
__device__ __constant__ float c_aw[3]   = {0.7f, 1.26f, 2.64f};
__device__ __constant__ float c_ah[3]   = {1.18f, 2.1f, 4.2f};
__device__ __constant__ float c_awah[3] = {0.826f, 2.646f, 11.088f};
// gate: iou>0.5 needs 2*pa > ga_min(>=924.16); thr[a] = ln(457/awah[a]) (safe superset)
__device__ __constant__ float c_gthr[3] = {6.315f, 5.150f, 3.717f};

// -------- persistent scratch (zero-initialized; self-resetting) --------
__device__ double   g_part[NBLKS];
__device__ float4   g_reca[LISTCAP];   // pxlo,pxhi,pylo,pyhi
__device__ float4   g_recb[LISTCAP];   // pa, sp(o11), batch(asint), 0
__device__ int      g_nlist;
__device__ unsigned g_sdone;           // stream blocks completed
__device__ unsigned g_adone;           // all blocks completed

__device__ __forceinline__ float softplusf(float x) {
    return fmaxf(x, 0.f) + __logf(1.f + __expf(-fabsf(x)));
}
__device__ __forceinline__ float bce_logit(float x, float t) {
    return softplusf(x) - t * x;
}
__device__ __forceinline__ float sigfast(float x) {
    return 1.f / (1.f + __expf(-x));
}

__device__ __forceinline__ bool cell_ignored(
    float o0, float o1, float o9, float o10, float aw, float ah,
    int i, int j, int cnt, const float4* lh, const float* ga)
{
    float pw = __expf(o9) * aw, ph = __expf(o10) * ah;
    float px = sigfast(o0) + (float)i;
    float py = sigfast(o1) + (float)j;
    float pxlo = px - 0.5f*pw, pxhi = px + 0.5f*pw;
    float pylo = py - 0.5f*ph, pyhi = py + 0.5f*ph;
    float pa = pw * ph;
    bool ig = false;
    for (int k = 0; k < cnt; k++) {
        float cw = fminf(pxhi, lh[k].y) - fmaxf(pxlo, lh[k].x);
        float ch = fminf(pyhi, lh[k].w) - fmaxf(pylo, lh[k].z);
        float inter = fmaxf(cw, 0.f) * fmaxf(ch, 0.f);
        if (3.f*inter > pa + ga[k]) ig = true;     // iou > 0.5
    }
    return ig;
}

__device__ __forceinline__ float iou_div(float x1,float y1,float w1,float h1,
                                         float x2,float y2,float w2,float h2) {
    float cw = fminf(x1+0.5f*w1, x2+0.5f*w2) - fmaxf(x1-0.5f*w1, x2-0.5f*w2);
    float ch = fminf(y1+0.5f*h1, y2+0.5f*h2) - fmaxf(y1-0.5f*h1, y2-0.5f*h2);
    float inter = (cw > 0.f && ch > 0.f) ? cw*ch : 0.f;
    return inter / (w1*h1 + w2*h2 - inter);
}

__global__ void __launch_bounds__(256, 3)
k_fused(const float* __restrict__ out,
        const float* __restrict__ tgt,
        float* __restrict__ d_out)
{
    __shared__ double s_wsum[8];
    __shared__ int    s_fin;
    int tid = threadIdx.x;
    double local = 0.0;

    if (blockIdx.x < SBLKS) {
        // ======== stream role: pure pass over ch 9/10/11, no GT, no syncs ========
        int t0 = blockIdx.x*768 + tid;
        float4 v9[3], v10[3], v11[3];
        const float* bp[3];
        int    bv[3], av[3], remv[3];
        #pragma unroll
        for (int k = 0; k < 3; k++) {
            int g = t0 + k*256;                    // exact cover
            int b = g / G4PB;
            int r = g - b*G4PB;
            int cell0 = r * 4;
            int a   = (cell0 >= 2*NPIX) ? 2 : (cell0 >= NPIX ? 1 : 0);
            int rem = cell0 - a*NPIX;
            const float* basep = out + (size_t)(b*NANC + a)*NCH*NPIX + rem;
            bp[k] = basep; bv[k] = b; av[k] = a; remv[k] = rem;
            v9[k]  = __ldcs(reinterpret_cast<const float4*>(basep + 9*NPIX));
            v10[k] = __ldcs(reinterpret_cast<const float4*>(basep + 10*NPIX));
            v11[k] = __ldcs(reinterpret_cast<const float4*>(basep + 11*NPIX));
        }
        float lf = 0.f;
        #pragma unroll
        for (int k = 0; k < 3; k++) {
            float a9[4]  = {v9[k].x,  v9[k].y,  v9[k].z,  v9[k].w};
            float a10[4] = {v10[k].x, v10[k].y, v10[k].z, v10[k].w};
            float a11[4] = {v11[k].x, v11[k].y, v11[k].z, v11[k].w};
            float gthr = c_gthr[av[k]];
            float aw = c_aw[av[k]], ah = c_ah[av[k]];
            float p = 1.f;
            #pragma unroll
            for (int s = 0; s < 4; s++) {
                p *= 1.f + __expf(a11[s]);
                bool want = (a9[s] + a10[s] > gthr);     // ~0.15% of cells
                unsigned wm = __ballot_sync(0xFFFFFFFFu, want);
                if (wm) {
                    int lane = tid & 31;
                    int leader = __ffs(wm) - 1;
                    int base2 = 0;
                    if (lane == leader) base2 = atomicAdd(&g_nlist, __popc(wm));
                    base2 = __shfl_sync(0xFFFFFFFFu, base2, leader);
                    if (want) {
                        int rank = __popc(wm & ((1u << lane) - 1u));
                        int idx  = base2 + rank;
                        if (idx < LISTCAP) {
                            // build self-contained record
                            float o0 = __ldcs(bp[k] + s);
                            float o1 = __ldcs(bp[k] + NPIX + s);
                            int cell = remv[k] + s;
                            int j = cell / NWW;
                            int i = cell - j*NWW;
                            float pw = __expf(a9[s])  * aw;
                            float ph = __expf(a10[s]) * ah;
                            float px = sigfast(o0) + (float)i;
                            float py = sigfast(o1) + (float)j;
                            g_reca[idx] = make_float4(px - 0.5f*pw, px + 0.5f*pw,
                                                      py - 0.5f*ph, py + 0.5f*ph);
                            g_recb[idx] = make_float4(pw*ph,
                                                      softplusf(a11[s]),
                                                      __int_as_float(bv[k]), 0.f);
                        }
                    }
                }
            }
            lf += __logf(p);
        }
        local = (double)lf;

        // slot write + release g_sdone
        #pragma unroll
        for (int off = 16; off > 0; off >>= 1)
            local += __shfl_down_sync(0xFFFFFFFFu, local, off);
        if ((tid & 31) == 0) s_wsum[tid >> 5] = local;
        __syncthreads();
        if (tid == 0) {
            double bs = 0.0;
            #pragma unroll
            for (int w = 0; w < 8; w++) bs += s_wsum[w];
            g_part[blockIdx.x] = bs;
            __threadfence();                      // release: records + slot
            atomicAdd(&g_sdone, 1u);
            unsigned old = atomicAdd(&g_adone, 1u);
            s_fin = (old == NBLKS - 1) ? 1 : 0;   // practically never for stream
        }
        __syncthreads();
    } else {
        // ======== target role: obj losses, then consume the record list ========
        __shared__ float    st[MAXT*12];
        __shared__ float4   s_lh[MAXT];
        __shared__ float    s_ga[MAXT];
        __shared__ int      s_flat[MAXT];
        __shared__ int      s_cls[MAXT];
        __shared__ unsigned s_m0, s_m1;

        int b = blockIdx.x - SBLKS;
        for (int i = tid; i < MAXT*12; i += 256) st[i] = tgt[b*MAXT*12 + i];
        __syncthreads();

        int t = tid;
        bool pos = (t < MAXT) && (st[t*12 + 1] > 0.f);
        if (t < 64) {
            unsigned bal = __ballot_sync(0xFFFFFFFFu, pos);
            if ((t & 31) == 0) { if (t < 32) s_m0 = bal; else s_m1 = bal; }
        }
        __syncthreads();
        int cnt = (~s_m0) ? (__ffs(~s_m0) - 1) : (32 + __ffs(~s_m1) - 1);
        if (cnt > MAXT) cnt = MAXT;

        float gx=0, gy=0, gw=0, gh=0, aw=0, ah=0;
        int best=0, gi=0, gj=0, flat=-1;
        if (t < MAXT) {
            const float* tb = st + t*12;
            gx = tb[1]*(float)NWW;  gy = tb[2]*(float)NHH;
            gw = tb[10]*NETWH;      gh = tb[11]*NETWH;
            s_ga[t] = gw*gh;
            s_lh[t] = make_float4(gx-0.5f*gw, gx+0.5f*gw, gy-0.5f*gh, gy+0.5f*gh);
            if (t < cnt) {
                float bestr = -1.f;
                #pragma unroll
                for (int a = 0; a < NANC; a++) {
                    float inter = fminf(gw, c_aw[a]) * fminf(gh, c_ah[a]);
                    float r = inter / (gw*gh + c_awah[a] - inter);
                    if (r > bestr) { bestr = r; best = a; }
                }
                gi = min(max((int)floorf(gx), 0), NWW-1);
                gj = min(max((int)floorf(gy), 0), NHH-1);
                flat = best*NPIX + gj*NWW + gi;
                aw = c_aw[best]; ah = c_ah[best];
            }
            s_flat[t] = flat;
            s_cls[t]  = (int)tb[0];
        }
        __syncthreads();

        if (t < cnt) {
            bool winner = true; unsigned mask = 0;
            for (int t2 = 0; t2 < cnt; t2++) {
                if (s_flat[t2] == flat) {
                    if (t2 > t) winner = false;
                    mask |= 1u << s_cls[t2];
                }
            }
            if (winner) {
                const float* tb = st + t*12;
                const float* basep = out + (size_t)(b*NANC + best)*NCH*NPIX
                                         + (gj*NWW + gi);
                float o[12];
                #pragma unroll
                for (int c = 0; c < 12; c++) o[c] = basep[c*NPIX];
                float cl[NCLS];
                #pragma unroll
                for (int c = 0; c < NCLS; c++) cl[c] = basep[(NLV + c)*NPIX];

                float l = 0.f;
                float tx = gx - (float)gi, ty = gy - (float)gj;
                l += bce_logit(o[0], tx) + bce_logit(o[1], ty);
                float r9 = logf(gw/aw), r10 = logf(gh/ah);
                float d9 = o[9]-r9, d10 = o[10]-r10;
                l += d9*d9 + d10*d10;
                float d2 = o[2]-tb[3], d3 = o[3]-tb[4], d4 = o[4]-tb[5];
                float ss = d2*d2 + d3*d3 + d4*d4;
                float dis = sqrtf(ss);
                if (dis <= BETA_C) l += 0.5f*ss/BETA_C;
                else               l += fabsf(d2)+fabsf(d3)+fabsf(d4) - 0.5f*BETA_C;
                float nrm = fmaxf(sqrtf(o[5]*o[5]+o[6]*o[6]+o[7]*o[7]+o[8]*o[8]), 1e-12f);
                l += fabsf(o[5]/nrm - tb[6]) + fabsf(o[6]/nrm - tb[7])
                   + fabsf(o[7]/nrm - tb[8]) + fabsf(o[8]/nrm - tb[9]);
                float px = sigfast(o[0]) + (float)gi;
                float py = sigfast(o[1]) + (float)gj;
                float pw = __expf(o[9])*aw, ph = __expf(o[10])*ah;
                float iou_t = iou_div(gx, gy, gw, gh, px, py, pw, ph);
                l += bce_logit(o[11], iou_t);
                #pragma unroll
                for (int c = 0; c < NCLS; c++) {
                    float tt = ((mask >> c) & 1u) ? 1.f : 0.f;
                    l += bce_logit(cl[c], tt);
                }
                // cancel the stream's softplus unless this cell is exact-ignored
                // (if ignored, the record-consumer below subtracts it instead)
                bool ig = cell_ignored(o[0], o[1], o[9], o[10], aw, ah, gi, gj,
                                       cnt, s_lh, s_ga);
                if (!ig) l -= __logf(1.f + __expf(o[11]));
                local = (double)l;
            }
        }

        // ---- wait for all stream blocks (all blocks co-resident: 425<=444) ----
        if (tid == 0) {
            while (atomicAdd(&g_sdone, 0u) < SBLKS) __nanosleep(128);
        }
        __syncthreads();
        __threadfence();                           // acquire

        // ---- consume list: subtract sp for truly-ignored cells of MY batch ----
        int n = atomicAdd(&g_nlist, 0);
        if (n > LISTCAP) n = LISTCAP;
        float lfix = 0.f;
        for (int e = tid; e < n; e += 256) {
            float4 rb = __ldcg(&g_recb[e]);
            if (__float_as_int(rb.z) == b) {
                float4 ra = __ldcg(&g_reca[e]);
                bool ig = false;
                for (int k = 0; k < cnt; k++) {
                    float cw = fminf(ra.y, s_lh[k].y) - fmaxf(ra.x, s_lh[k].x);
                    float ch = fminf(ra.w, s_lh[k].w) - fmaxf(ra.z, s_lh[k].z);
                    float inter = fmaxf(cw, 0.f) * fmaxf(ch, 0.f);
                    if (3.f*inter > rb.x + s_ga[k]) ig = true;
                }
                if (ig) lfix -= rb.y;
            }
        }
        local += (double)lfix;

        // slot write
        #pragma unroll
        for (int off = 16; off > 0; off >>= 1)
            local += __shfl_down_sync(0xFFFFFFFFu, local, off);
        if ((tid & 31) == 0) s_wsum[tid >> 5] = local;
        __syncthreads();
        if (tid == 0) {
            double bs = 0.0;
            #pragma unroll
            for (int w = 0; w < 8; w++) bs += s_wsum[w];
            g_part[blockIdx.x] = bs;
            __threadfence();
            unsigned old = atomicAdd(&g_adone, 1u);
            s_fin = (old == NBLKS - 1) ? 1 : 0;
        }
        __syncthreads();
    }

    // ============ last-arrived block: parallel sum + finalize + reset ============
    if (s_fin) {
        double v = 0.0;
        for (int i = tid; i < NBLKS; i += 256) v += g_part[i];
        #pragma unroll
        for (int off = 16; off > 0; off >>= 1)
            v += __shfl_down_sync(0xFFFFFFFFu, v, off);
        if ((tid & 31) == 0) s_wsum[tid >> 5] = v;
        __syncthreads();
        if (tid == 0) {
            double tot = 0.0;
            #pragma unroll
            for (int w = 0; w < 8; w++) tot += s_wsum[w];
            d_out[0] = (float)(tot * (1.0/(double)NBATCH));
            g_nlist = 0;                          // self-reset for graph replay
            g_sdone = 0u;
            __threadfence();
            g_adone = 0u;
        }
    }
}

extern "C" void kernel_launch(void* const* d_in, const int* in_sizes, int n_in,
                              void* d_out, int out_size) {
    const float* out  = nullptr;
    const float* tgt  = nullptr;
    for (int k = 0; k < n_in; k++) {
        if      (in_sizes[k] == NBATCH*NANC*NCH*NPIX) out  = (const float*)d_in[k];
        else if (in_sizes[k] == NBATCH*MAXT*NLV)      tgt  = (const float*)d_in[k];
    }
    k_fused<<<NBLKS, 256>>>(out, tgt, (float*)d_out);
}

// round 16
// speedup vs baseline: 1.0755x; 1.0755x over previous
#include <cuda_runtime.h>
#include <math.h>

#define NBATCH 64
#define NANC   3
#define NCLS   13
#define NHH    76
#define NWW    76
#define NPIX   (NHH*NWW)          // 5776
#define NANCH  (NANC*NPIX)        // 17328
#define MAXT   50
#define NLV    12
#define NCH    (NLV+NCLS)         // 25
#define BETA_C 0.028f
#define NETWH  608.0f

#define G4PB    (NANCH/4)         // 4332 float4-groups per batch
#define G4TOT   (NBATCH*G4PB)     // 277248
#define SBLKS   361               // 361*256*3 == 277248 EXACT cover
#define NBLKS   (SBLKS+NBATCH)    // 425 blocks total

// anchors fixed: [[0.7,1.18],[1.26,2.1],[2.64,4.2]]
__device__ __constant__ float c_aw[3]   = {0.7f, 1.26f, 2.64f};
__device__ __constant__ float c_ah[3]   = {1.18f, 2.1f, 4.2f};
__device__ __constant__ float c_awah[3] = {0.826f, 2.646f, 11.088f};
// iou>0.5 requires 2*pa > ga_min (every valid GT area >= 924.16)
// thr[a] = ln(457/awah[a])  (457 < 462 -> safe superset, ~0.15% hit rate)
__device__ __constant__ float c_gthr[3] = {6.315f, 5.150f, 3.717f};

// -------- persistent scratch (zero-initialized; self-resetting) --------
__device__ double   g_part[NBLKS];
__device__ unsigned g_done;

__device__ __forceinline__ float softplusf(float x) {
    return fmaxf(x, 0.f) + __logf(1.f + __expf(-fabsf(x)));
}
__device__ __forceinline__ float bce_logit(float x, float t) {
    return softplusf(x) - t * x;      // == bce(sigmoid(x), t)
}
__device__ __forceinline__ float sigfast(float x) {
    return 1.f / (1.f + __expf(-x));
}

// exact ignore test reading GT straight from tgt (input; L2-hot).
// Walks rows until first invalid (reference cumprod-validity).
__device__ __forceinline__ bool ignored_from_tgt(
    const float* __restrict__ tgt, int b,
    float pxlo, float pxhi, float pylo, float pyhi, float pa)
{
    const float* tb = tgt + b*MAXT*12;
    bool ig = false;
    for (int k = 0; k < MAXT; k++, tb += 12) {
        float x = tb[1];
        if (!(x > 0.f)) break;
        float gx = x     * (float)NWW;
        float gy = tb[2] * (float)NHH;
        float gw = tb[10] * NETWH;
        float gh = tb[11] * NETWH;
        float cw = fminf(pxhi, gx + 0.5f*gw) - fmaxf(pxlo, gx - 0.5f*gw);
        float ch = fminf(pyhi, gy + 0.5f*gh) - fmaxf(pylo, gy - 0.5f*gh);
        float inter = fmaxf(cw, 0.f) * fmaxf(ch, 0.f);
        if (3.f*inter > pa + gw*gh) ig = true;     // iou > 0.5
    }
    return ig;
}

__device__ __forceinline__ bool cell_ignored_sh(
    float o0, float o1, float o9, float o10, float aw, float ah,
    int i, int j, int cnt, const float4* lh, const float* ga)
{
    float pw = __expf(o9) * aw, ph = __expf(o10) * ah;
    float px = sigfast(o0) + (float)i;
    float py = sigfast(o1) + (float)j;
    float pxlo = px - 0.5f*pw, pxhi = px + 0.5f*pw;
    float pylo = py - 0.5f*ph, pyhi = py + 0.5f*ph;
    float pa = pw * ph;
    bool ig = false;
    for (int k = 0; k < cnt; k++) {
        float cw = fminf(pxhi, lh[k].y) - fmaxf(pxlo, lh[k].x);
        float ch = fminf(pyhi, lh[k].w) - fmaxf(pylo, lh[k].z);
        float inter = fmaxf(cw, 0.f) * fmaxf(ch, 0.f);
        if (3.f*inter > pa + ga[k]) ig = true;
    }
    return ig;
}

__device__ __forceinline__ float iou_div(float x1,float y1,float w1,float h1,
                                         float x2,float y2,float w2,float h2) {
    float cw = fminf(x1+0.5f*w1, x2+0.5f*w2) - fmaxf(x1-0.5f*w1, x2-0.5f*w2);
    float ch = fminf(y1+0.5f*h1, y2+0.5f*h2) - fmaxf(y1-0.5f*h1, y2-0.5f*h2);
    float inter = (cw > 0.f && ch > 0.f) ? cw*ch : 0.f;
    return inter / (w1*h1 + w2*h2 - inter);
}

__global__ void __launch_bounds__(256, 4)
k_fused(const float* __restrict__ out,
        const float* __restrict__ tgt,
        float* __restrict__ d_out)
{
    __shared__ double s_wsum[8];
    __shared__ int    s_fin;
    int tid = threadIdx.x;
    double local = 0.0;

    if (blockIdx.x < SBLKS) {
        // ===== stream role: zero preamble, zero shared, zero syncs, no GT =====
        int t0 = blockIdx.x*768 + tid;
        float4 v9[3], v10[3], v11[3];
        const float* bp[3];
        int    bv[3], av[3], remv[3];
        #pragma unroll
        for (int k = 0; k < 3; k++) {
            int g = t0 + k*256;                    // exact cover, no bounds check
            int b = g / G4PB;
            int r = g - b*G4PB;
            int cell0 = r * 4;
            int a   = (cell0 >= 2*NPIX) ? 2 : (cell0 >= NPIX ? 1 : 0);
            int rem = cell0 - a*NPIX;
            const float* basep = out + (size_t)(b*NANC + a)*NCH*NPIX + rem;
            bp[k] = basep; bv[k] = b; av[k] = a; remv[k] = rem;
            v9[k]  = __ldcs(reinterpret_cast<const float4*>(basep + 9*NPIX));
            v10[k] = __ldcs(reinterpret_cast<const float4*>(basep + 10*NPIX));
            v11[k] = __ldcs(reinterpret_cast<const float4*>(basep + 11*NPIX));
        }
        float lf = 0.f;
        #pragma unroll
        for (int k = 0; k < 3; k++) {
            float a9[4]  = {v9[k].x,  v9[k].y,  v9[k].z,  v9[k].w};
            float a10[4] = {v10[k].x, v10[k].y, v10[k].z, v10[k].w};
            float a11[4] = {v11[k].x, v11[k].y, v11[k].z, v11[k].w};
            float gthr = c_gthr[av[k]];
            float aw = c_aw[av[k]], ah = c_ah[av[k]];
            float p = 1.f;
            #pragma unroll
            for (int s = 0; s < 4; s++) {
                p *= 1.f + __expf(a11[s]);         // softplus via log-of-product
                if (a9[s] + a10[s] > gthr) {       // ~0.15% of cells
                    float o0 = __ldcs(bp[k] + s);
                    float o1 = __ldcs(bp[k] + NPIX + s);
                    int cell = remv[k] + s;
                    int j = cell / NWW;
                    int i = cell - j*NWW;
                    float pw = __expf(a9[s])  * aw;
                    float ph = __expf(a10[s]) * ah;
                    float px = sigfast(o0) + (float)i;
                    float py = sigfast(o1) + (float)j;
                    if (ignored_from_tgt(tgt, bv[k],
                                         px - 0.5f*pw, px + 0.5f*pw,
                                         py - 0.5f*ph, py + 0.5f*ph, pw*ph))
                        lf -= softplusf(a11[s]);   // cancel the product term
                }
            }
            lf += __logf(p);
        }
        local = (double)lf;
    } else {
        // ===== target role: obj-cell losses for one batch =====
        __shared__ float    st[MAXT*12];
        __shared__ float4   s_lh[MAXT];
        __shared__ float    s_ga[MAXT];
        __shared__ int      s_flat[MAXT];
        __shared__ int      s_cls[MAXT];
        __shared__ unsigned s_m0, s_m1;

        int b = blockIdx.x - SBLKS;
        for (int i = tid; i < MAXT*12; i += 256) st[i] = tgt[b*MAXT*12 + i];
        __syncthreads();

        int t = tid;
        bool pos = (t < MAXT) && (st[t*12 + 1] > 0.f);
        if (t < 64) {
            unsigned bal = __ballot_sync(0xFFFFFFFFu, pos);
            if ((t & 31) == 0) { if (t < 32) s_m0 = bal; else s_m1 = bal; }
        }
        __syncthreads();
        int cnt = (~s_m0) ? (__ffs(~s_m0) - 1) : (32 + __ffs(~s_m1) - 1);
        if (cnt > MAXT) cnt = MAXT;

        float gx=0, gy=0, gw=0, gh=0, aw=0, ah=0;
        int best=0, gi=0, gj=0, flat=-1;
        if (t < MAXT) {
            const float* tb = st + t*12;
            gx = tb[1]*(float)NWW;  gy = tb[2]*(float)NHH;
            gw = tb[10]*NETWH;      gh = tb[11]*NETWH;
            s_ga[t] = gw*gh;
            s_lh[t] = make_float4(gx-0.5f*gw, gx+0.5f*gw, gy-0.5f*gh, gy+0.5f*gh);
            if (t < cnt) {
                float bestr = -1.f;
                #pragma unroll
                for (int a = 0; a < NANC; a++) {
                    float inter = fminf(gw, c_aw[a]) * fminf(gh, c_ah[a]);
                    float r = inter / (gw*gh + c_awah[a] - inter);
                    if (r > bestr) { bestr = r; best = a; }
                }
                gi = min(max((int)floorf(gx), 0), NWW-1);
                gj = min(max((int)floorf(gy), 0), NHH-1);
                flat = best*NPIX + gj*NWW + gi;
                aw = c_aw[best]; ah = c_ah[best];
            }
            s_flat[t] = flat;
            s_cls[t]  = (int)tb[0];
        }
        __syncthreads();

        if (t < cnt) {
            bool winner = true; unsigned mask = 0;
            for (int t2 = 0; t2 < cnt; t2++) {
                if (s_flat[t2] == flat) {
                    if (t2 > t) winner = false;
                    mask |= 1u << s_cls[t2];
                }
            }
            if (winner) {
                const float* tb = st + t*12;
                const float* basep = out + (size_t)(b*NANC + best)*NCH*NPIX
                                         + (gj*NWW + gi);
                float o[12];
                #pragma unroll
                for (int c = 0; c < 12; c++) o[c] = basep[c*NPIX];
                float cl[NCLS];
                #pragma unroll
                for (int c = 0; c < NCLS; c++) cl[c] = basep[(NLV + c)*NPIX];

                float l = 0.f;
                float tx = gx - (float)gi, ty = gy - (float)gj;
                l += bce_logit(o[0], tx) + bce_logit(o[1], ty);
                float r9 = logf(gw/aw), r10 = logf(gh/ah);
                float d9 = o[9]-r9, d10 = o[10]-r10;
                l += d9*d9 + d10*d10;
                float d2 = o[2]-tb[3], d3 = o[3]-tb[4], d4 = o[4]-tb[5];
                float ss = d2*d2 + d3*d3 + d4*d4;
                float dis = sqrtf(ss);
                if (dis <= BETA_C) l += 0.5f*ss/BETA_C;
                else               l += fabsf(d2)+fabsf(d3)+fabsf(d4) - 0.5f*BETA_C;
                float nrm = fmaxf(sqrtf(o[5]*o[5]+o[6]*o[6]+o[7]*o[7]+o[8]*o[8]), 1e-12f);
                l += fabsf(o[5]/nrm - tb[6]) + fabsf(o[6]/nrm - tb[7])
                   + fabsf(o[7]/nrm - tb[8]) + fabsf(o[8]/nrm - tb[9]);
                float px = sigfast(o[0]) + (float)gi;
                float py = sigfast(o[1]) + (float)gj;
                float pw = __expf(o[9])*aw, ph = __expf(o[10])*ah;
                float iou_t = iou_div(gx, gy, gw, gh, px, py, pw, ph);
                l += bce_logit(o[11], iou_t);
                #pragma unroll
                for (int c = 0; c < NCLS; c++) {
                    float tt = ((mask >> c) & 1u) ? 1.f : 0.f;
                    l += bce_logit(cl[c], tt);
                }
                // cancel the stream's softplus unless this cell is exact-ignored
                // (gate superset guarantees the stream's decision matches)
                bool ig = cell_ignored_sh(o[0], o[1], o[9], o[10], aw, ah, gi, gj,
                                          cnt, s_lh, s_ga);
                if (!ig) l -= __logf(1.f + __expf(o[11]));
                local = (double)l;
            }
        }
    }

    // ============ per-block slot write + last-done-block finalize ============
    #pragma unroll
    for (int off = 16; off > 0; off >>= 1)
        local += __shfl_down_sync(0xFFFFFFFFu, local, off);
    if ((tid & 31) == 0) s_wsum[tid >> 5] = local;
    __syncthreads();
    if (tid == 0) {
        double bs = 0.0;
        #pragma unroll
        for (int w = 0; w < 8; w++) bs += s_wsum[w];
        g_part[blockIdx.x] = bs;
        __threadfence();
        unsigned old = atomicAdd(&g_done, 1u);
        s_fin = (old == NBLKS - 1) ? 1 : 0;
    }
    __syncthreads();

    if (s_fin) {
        __threadfence();                           // acquire
        double v = 0.0;
        for (int i = tid; i < NBLKS; i += 256) v += g_part[i];
        #pragma unroll
        for (int off = 16; off > 0; off >>= 1)
            v += __shfl_down_sync(0xFFFFFFFFu, v, off);
        if ((tid & 31) == 0) s_wsum[tid >> 5] = v;
        __syncthreads();
        if (tid == 0) {
            double tot = 0.0;
            #pragma unroll
            for (int w = 0; w < 8; w++) tot += s_wsum[w];
            d_out[0] = (float)(tot * (1.0/(double)NBATCH));
            __threadfence();
            g_done = 0u;                           // self-reset for graph replay
        }
    }
}

extern "C" void kernel_launch(void* const* d_in, const int* in_sizes, int n_in,
                              void* d_out, int out_size) {
    const float* out  = nullptr;
    const float* tgt  = nullptr;
    for (int k = 0; k < n_in; k++) {
        if      (in_sizes[k] == NBATCH*NANC*NCH*NPIX) out  = (const float*)d_in[k];
        else if (in_sizes[k] == NBATCH*MAXT*NLV)      tgt  = (const float*)d_in[k];
    }
    k_fused<<<NBLKS, 256>>>(out, tgt, (float*)d_out);
}

// round 17
// speedup vs baseline: 1.6177x; 1.5042x over previous
#include <cuda_runtime.h>
#include <math.h>

#define NBATCH 64
#define NANC   3
#define NCLS   13
#define NHH    76
#define NWW    76
#define NPIX   (NHH*NWW)          // 5776
#define NANCH  (NANC*NPIX)        // 17328
#define MAXT   50
#define NLV    12
#define NCH    (NLV+NCLS)         // 25
#define BETA_C 0.028f
#define NETWH  608.0f

#define G4PB    (NANCH/4)         // 4332 float4-groups per batch
#define G4TOT   (NBATCH*G4PB)     // 277248
#define SBLKS   361               // 361*256*3 == 277248 EXACT cover
#define NBLKS   (SBLKS+NBATCH)    // 425 blocks total

// anchors fixed: [[0.7,1.18],[1.26,2.1],[2.64,4.2]]
__device__ __constant__ float c_aw[3]   = {0.7f, 1.26f, 2.64f};
__device__ __constant__ float c_ah[3]   = {1.18f, 2.1f, 4.2f};
__device__ __constant__ float c_awah[3] = {0.826f, 2.646f, 11.088f};
// iou>0.5 requires 2*pa > ga_min (every valid GT area >= 924.16)
// thr[a] = ln(457/awah[a])  (457 < 462 -> safe superset)
__device__ __constant__ float c_gthr[3] = {6.315f, 5.150f, 3.717f};

// -------- persistent scratch (zero-initialized; self-resetting) --------
__device__ double   g_part[NBLKS];
__device__ unsigned g_done;

__device__ __forceinline__ float softplusf(float x) {
    return fmaxf(x, 0.f) + __logf(1.f + __expf(-fabsf(x)));
}
__device__ __forceinline__ float bce_logit(float x, float t) {
    return softplusf(x) - t * x;
}
__device__ __forceinline__ float sigfast(float x) {
    return 1.f / (1.f + __expf(-x));
}

__device__ __forceinline__ float iou_div(float x1,float y1,float w1,float h1,
                                         float x2,float y2,float w2,float h2) {
    float cw = fminf(x1+0.5f*w1, x2+0.5f*w2) - fmaxf(x1-0.5f*w1, x2-0.5f*w2);
    float ch = fminf(y1+0.5f*h1, y2+0.5f*h2) - fmaxf(y1-0.5f*h1, y2-0.5f*h2);
    float inter = (cw > 0.f && ch > 0.f) ? cw*ch : 0.f;
    return inter / (w1*h1 + w2*h2 - inter);
}

__global__ void __launch_bounds__(256, 4)
k_fused(const float* __restrict__ out,
        const float* __restrict__ tgt,
        float* __restrict__ d_out)
{
    __shared__ double s_wsum[8];
    __shared__ int    s_fin;
    int tid = threadIdx.x;
    double local = 0.0;

    if (blockIdx.x < SBLKS) {
        // ===== stream role: exact-cover groups + minimal shared-GT preamble =====
        __shared__ float4 p_lh[2][MAXT];   // xlo,xhi,ylo,yhi
        __shared__ float  p_ga[2][MAXT];   // area
        __shared__ float  p_vx[2][MAXT];   // raw x (validity via break)

        int gBase = blockIdx.x * 768;
        int b0 = gBase / G4PB;
        int b1 = (gBase + 767) / G4PB;     // <= b0+1, <= 63

        // preamble: 100 threads load 2 batches' GT rows; no ballots, one sync
        if (tid < 100) {
            int seg = tid / MAXT;          // 0 or 1
            int row = tid - seg*MAXT;
            int bb  = (seg == 0) ? b0 : b1;
            const float* p = tgt + (bb*MAXT + row)*12;
            float x  = p[1];
            float gx = x    * (float)NWW;
            float gy = p[2] * (float)NHH;
            float gw = p[10] * NETWH;
            float gh = p[11] * NETWH;
            p_lh[seg][row] = make_float4(gx-0.5f*gw, gx+0.5f*gw,
                                         gy-0.5f*gh, gy+0.5f*gh);
            p_ga[seg][row] = gw*gh;
            p_vx[seg][row] = x;
        }

        // streaming loads (9 independent LDG.128), issued before the sync
        int t0 = gBase + tid;
        float4 v9[3], v10[3], v11[3];
        const float* bp[3];
        int    bv[3], av[3], remv[3];
        #pragma unroll
        for (int k = 0; k < 3; k++) {
            int g = t0 + k*256;            // exact cover, no bounds check
            int b = g / G4PB;
            int r = g - b*G4PB;
            int cell0 = r * 4;
            int a   = (cell0 >= 2*NPIX) ? 2 : (cell0 >= NPIX ? 1 : 0);
            int rem = cell0 - a*NPIX;
            const float* basep = out + (size_t)(b*NANC + a)*NCH*NPIX + rem;
            bp[k] = basep; bv[k] = b; av[k] = a; remv[k] = rem;
            v9[k]  = __ldcs(reinterpret_cast<const float4*>(basep + 9*NPIX));
            v10[k] = __ldcs(reinterpret_cast<const float4*>(basep + 10*NPIX));
            v11[k] = __ldcs(reinterpret_cast<const float4*>(basep + 11*NPIX));
        }
        __syncthreads();                   // preamble visible

        float lf = 0.f;
        #pragma unroll
        for (int k = 0; k < 3; k++) {
            float a9[4]  = {v9[k].x,  v9[k].y,  v9[k].z,  v9[k].w};
            float a10[4] = {v10[k].x, v10[k].y, v10[k].z, v10[k].w};
            float a11[4] = {v11[k].x, v11[k].y, v11[k].z, v11[k].w};
            float gthr = c_gthr[av[k]];
            float aw = c_aw[av[k]], ah = c_ah[av[k]];
            int   seg = (bv[k] == b0) ? 0 : 1;
            float p = 1.f;
            #pragma unroll
            for (int s = 0; s < 4; s++) {
                p *= 1.f + __expf(a11[s]);       // softplus via log-of-product
                if (a9[s] + a10[s] > gthr) {     // rare candidate (~0.15%)
                    float o0 = __ldcs(bp[k] + s);
                    float o1 = __ldcs(bp[k] + NPIX + s);
                    int cell = remv[k] + s;
                    int j = cell / NWW;
                    int i = cell - j*NWW;
                    float pw = __expf(a9[s])  * aw;
                    float ph = __expf(a10[s]) * ah;
                    float px = sigfast(o0) + (float)i;
                    float py = sigfast(o1) + (float)j;
                    float pxlo = px - 0.5f*pw, pxhi = px + 0.5f*pw;
                    float pylo = py - 0.5f*ph, pyhi = py + 0.5f*ph;
                    float pa = pw * ph;
                    bool ig = false;
                    for (int t = 0; t < MAXT; t++) {
                        if (!(p_vx[seg][t] > 0.f)) break;   // cumprod validity
                        float4 lh = p_lh[seg][t];
                        float cw = fminf(pxhi, lh.y) - fmaxf(pxlo, lh.x);
                        float ch = fminf(pyhi, lh.w) - fmaxf(pylo, lh.z);
                        float inter = fmaxf(cw, 0.f) * fmaxf(ch, 0.f);
                        if (3.f*inter > pa + p_ga[seg][t]) ig = true;
                    }
                    if (ig) lf -= softplusf(a11[s]);
                }
            }
            lf += __logf(p);
        }
        local = (double)lf;
    } else {
        // ===== target role: obj-cell losses for one batch =====
        __shared__ float    st[MAXT*12];
        __shared__ float4   s_lh[MAXT];
        __shared__ float    s_ga[MAXT];
        __shared__ int      s_flat[MAXT];
        __shared__ int      s_cls[MAXT];
        __shared__ unsigned s_m0, s_m1;

        int b = blockIdx.x - SBLKS;
        for (int i = tid; i < MAXT*12; i += 256) st[i] = tgt[b*MAXT*12 + i];
        __syncthreads();

        int t = tid;
        bool pos = (t < MAXT) && (st[t*12 + 1] > 0.f);
        if (t < 64) {
            unsigned bal = __ballot_sync(0xFFFFFFFFu, pos);
            if ((t & 31) == 0) { if (t < 32) s_m0 = bal; else s_m1 = bal; }
        }
        __syncthreads();
        int cnt = (~s_m0) ? (__ffs(~s_m0) - 1) : (32 + __ffs(~s_m1) - 1);
        if (cnt > MAXT) cnt = MAXT;

        float gx=0, gy=0, gw=0, gh=0, aw=0, ah=0;
        int best=0, gi=0, gj=0, flat=-1;
        if (t < MAXT) {
            const float* tb = st + t*12;
            gx = tb[1]*(float)NWW;  gy = tb[2]*(float)NHH;
            gw = tb[10]*NETWH;      gh = tb[11]*NETWH;
            s_ga[t] = gw*gh;
            s_lh[t] = make_float4(gx-0.5f*gw, gx+0.5f*gw, gy-0.5f*gh, gy+0.5f*gh);
            if (t < cnt) {
                float bestr = -1.f;
                #pragma unroll
                for (int a = 0; a < NANC; a++) {
                    float inter = fminf(gw, c_aw[a]) * fminf(gh, c_ah[a]);
                    float r = inter / (gw*gh + c_awah[a] - inter);
                    if (r > bestr) { bestr = r; best = a; }
                }
                gi = min(max((int)floorf(gx), 0), NWW-1);
                gj = min(max((int)floorf(gy), 0), NHH-1);
                flat = best*NPIX + gj*NWW + gi;
                aw = c_aw[best]; ah = c_ah[best];
            }
            s_flat[t] = flat;
            s_cls[t]  = (int)tb[0];
        }
        __syncthreads();

        if (t < cnt) {
            bool winner = true; unsigned mask = 0;
            for (int t2 = 0; t2 < cnt; t2++) {
                if (s_flat[t2] == flat) {
                    if (t2 > t) winner = false;
                    mask |= 1u << s_cls[t2];
                }
            }
            if (winner) {
                const float* tb = st + t*12;
                const float* basep = out + (size_t)(b*NANC + best)*NCH*NPIX
                                         + (gj*NWW + gi);
                float o[12];
                #pragma unroll
                for (int c = 0; c < 12; c++) o[c] = basep[c*NPIX];
                float cl[NCLS];
                #pragma unroll
                for (int c = 0; c < NCLS; c++) cl[c] = basep[(NLV + c)*NPIX];

                float l = 0.f;
                float tx = gx - (float)gi, ty = gy - (float)gj;
                l += bce_logit(o[0], tx) + bce_logit(o[1], ty);
                float r9 = logf(gw/aw), r10 = logf(gh/ah);
                float d9 = o[9]-r9, d10 = o[10]-r10;
                l += d9*d9 + d10*d10;
                float d2 = o[2]-tb[3], d3 = o[3]-tb[4], d4 = o[4]-tb[5];
                float ss = d2*d2 + d3*d3 + d4*d4;
                float dis = sqrtf(ss);
                if (dis <= BETA_C) l += 0.5f*ss/BETA_C;
                else               l += fabsf(d2)+fabsf(d3)+fabsf(d4) - 0.5f*BETA_C;
                float nrm = fmaxf(sqrtf(o[5]*o[5]+o[6]*o[6]+o[7]*o[7]+o[8]*o[8]), 1e-12f);
                l += fabsf(o[5]/nrm - tb[6]) + fabsf(o[6]/nrm - tb[7])
                   + fabsf(o[7]/nrm - tb[8]) + fabsf(o[8]/nrm - tb[9]);
                float px = sigfast(o[0]) + (float)gi;
                float py = sigfast(o[1]) + (float)gj;
                float pw = __expf(o[9])*aw, ph = __expf(o[10])*ah;
                float iou_t = iou_div(gx, gy, gw, gh, px, py, pw, ph);
                l += bce_logit(o[11], iou_t);
                #pragma unroll
                for (int c = 0; c < NCLS; c++) {
                    float tt = ((mask >> c) & 1u) ? 1.f : 0.f;
                    l += bce_logit(cl[c], tt);
                }
                // cancel the stream's softplus unless this cell is exact-ignored
                {
                    float pw2 = __expf(o[9])*aw, ph2 = __expf(o[10])*ah;
                    float px2 = sigfast(o[0]) + (float)gi;
                    float py2 = sigfast(o[1]) + (float)gj;
                    float pxlo = px2 - 0.5f*pw2, pxhi = px2 + 0.5f*pw2;
                    float pylo = py2 - 0.5f*ph2, pyhi = py2 + 0.5f*ph2;
                    float pa = pw2 * ph2;
                    bool ig = false;
                    for (int k = 0; k < cnt; k++) {
                        float cw = fminf(pxhi, s_lh[k].y) - fmaxf(pxlo, s_lh[k].x);
                        float ch = fminf(pyhi, s_lh[k].w) - fmaxf(pylo, s_lh[k].z);
                        float inter = fmaxf(cw, 0.f) * fmaxf(ch, 0.f);
                        if (3.f*inter > pa + s_ga[k]) ig = true;
                    }
                    if (!ig) l -= __logf(1.f + __expf(o[11]));
                }
                local = (double)l;
            }
        }
    }

    // ============ per-block slot write + last-done-block finalize ============
    #pragma unroll
    for (int off = 16; off > 0; off >>= 1)
        local += __shfl_down_sync(0xFFFFFFFFu, local, off);
    if ((tid & 31) == 0) s_wsum[tid >> 5] = local;
    __syncthreads();
    if (tid == 0) {
        double bs = 0.0;
        #pragma unroll
        for (int w = 0; w < 8; w++) bs += s_wsum[w];
        g_part[blockIdx.x] = bs;
        __threadfence();
        unsigned old = atomicAdd(&g_done, 1u);
        s_fin = (old == NBLKS - 1) ? 1 : 0;
    }
    __syncthreads();

    if (s_fin) {
        __threadfence();                           // acquire
        double v = 0.0;
        for (int i = tid; i < NBLKS; i += 256) v += g_part[i];
        #pragma unroll
        for (int off = 16; off > 0; off >>= 1)
            v += __shfl_down_sync(0xFFFFFFFFu, v, off);
        if ((tid & 31) == 0) s_wsum[tid >> 5] = v;
        __syncthreads();
        if (tid == 0) {
            double tot = 0.0;
            #pragma unroll
            for (int w = 0; w < 8; w++) tot += s_wsum[w];
            d_out[0] = (float)(tot * (1.0/(double)NBATCH));
            __threadfence();
            g_done = 0u;                           // self-reset for graph replay
        }
    }
}

extern "C" void kernel_launch(void* const* d_in, const int* in_sizes, int n_in,
                              void* d_out, int out_size) {
    const float* out  = nullptr;
    const float* tgt  = nullptr;
    for (int k = 0; k < n_in; k++) {
        if      (in_sizes[k] == NBATCH*NANC*NCH*NPIX) out  = (const float*)d_in[k];
        else if (in_sizes[k] == NBATCH*MAXT*NLV)      tgt  = (const float*)d_in[k];
    }
    k_fused<<<NBLKS, 256>>>(out, tgt, (float*)d_out);
}